// round 17
// baseline (speedup 1.0000x reference)
#include <cuda_runtime.h>
#include <cuda_fp16.h>
#include <math.h>
#include <stdint.h>

#define BATCH 8
#define SEQ   4096
#define HID   256
#define NF    6

// Precombined per-batch weights, TRANSPOSED to [b][n][h], fp16.
__device__ __half g_B[BATCH * HID * HID];   // 1 MB (L2-resident)

// ===========================================================================
// Helpers
// ===========================================================================
__device__ __forceinline__ uint32_t smem_u32(const void* p) {
    uint32_t a;
    asm("{ .reg .u64 t; cvta.to.shared.u64 t, %1; cvt.u32.u64 %0, t; }" : "=r"(a) : "l"(p));
    return a;
}
__device__ __forceinline__ void cp_async16(uint32_t dst, const void* src) {
    asm volatile("cp.async.ca.shared.global [%0], [%1], 16;" :: "r"(dst), "l"(src));
}
#define CP_COMMIT()  asm volatile("cp.async.commit_group;" ::: "memory")
#define CP_WAIT(n)   asm volatile("cp.async.wait_group %0;" :: "n"(n) : "memory")

__device__ __forceinline__ void ldmx4(uint32_t a, uint32_t r[4]) {
    asm volatile("ldmatrix.sync.aligned.m8n8.x4.shared.b16 {%0,%1,%2,%3}, [%4];"
                 : "=r"(r[0]), "=r"(r[1]), "=r"(r[2]), "=r"(r[3]) : "r"(a));
}
__device__ __forceinline__ void mma16816(float c[4], const uint32_t a[4], const uint32_t b[2]) {
    asm volatile(
        "mma.sync.aligned.m16n8k16.row.col.f32.f16.f16.f32 "
        "{%0,%1,%2,%3},{%4,%5,%6,%7},{%8,%9},{%0,%1,%2,%3};"
        : "+f"(c[0]), "+f"(c[1]), "+f"(c[2]), "+f"(c[3])
        : "r"(a[0]), "r"(a[1]), "r"(a[2]), "r"(a[3]), "r"(b[0]), "r"(b[1]));
}

// Swizzled byte offset inside a [rows][64 fp16] tile (128B rows, XOR swizzle)
__device__ __forceinline__ uint32_t sw_off(int r, int k) {
    int c = k >> 3;
    return (uint32_t)((r << 7) + ((c ^ (r & 7)) << 4) + ((k & 7) << 1));
}

// ===========================================================================
// Kernel 1: build combined weights, transposed, fp16. grid (32, 8), 256 thr.
//   g_B[b][n][h] = fp16( sum_f W[f][h][n] * sin(freq_f*t_b + phase[f][n]) )
// ===========================================================================
__global__ __launch_bounds__(256) void build_M_kernel(
    const float* __restrict__ W,      // [F, H, H]
    const float* __restrict__ phase,  // [F, H]
    const float* __restrict__ t)      // [B, 1]
{
    __shared__ __half s_hi[8][HID];

    const int b  = blockIdx.y;
    const int h0 = blockIdx.x * 8;
    const int k  = threadIdx.x;
    const float tb = t[b];
    const float freqs[NF] = {1.f, 2.f, 4.f, 8.f, 7.f, 5.f};
    float res[NF];
#pragma unroll
    for (int f = 0; f < NF; f++) res[f] = sinf(freqs[f] * tb + phase[f * HID + k]);

#pragma unroll
    for (int hl = 0; hl < 8; hl++) {
        float acc = 0.f;
#pragma unroll
        for (int f = 0; f < NF; f++)
            acc = fmaf(W[((size_t)f * HID + h0 + hl) * HID + k], res[f], acc);
        s_hi[hl][k] = __float2half_rn(acc);
    }
    __syncthreads();

    const int n = k;
    __half th[8];
#pragma unroll
    for (int j = 0; j < 8; j++) th[j] = s_hi[j][n];
    *(uint4*)&g_B[((size_t)b * HID + n) * HID + h0] = *(uint4*)th;
}

// ===========================================================================
// Kernel 2: fully-resident fp16 mma.sync GEMM, ZERO mainloop barriers.
// CTA = 64 rows x 128 cols, K=256 entirely resident:
//   A 64x256 fp16 (32 KB, converted from fp32 in prologue)
//   B 128x256 fp16 (64 KB, cp.async from L2-resident g_B)
// One sync after load; then 16 unconstrained k-steps per warp.
// 96 KB smem -> 2 CTAs/SM. grid (2, 64, 8) = 1024 CTAs (~3.5 waves,
// natural load/compute overlap across CTAs).
// ===========================================================================
#define OFF_A      0                   // 4 chunk-tiles x 8 KB = 32 KB
#define OFF_B      32768               // 4 chunk-tiles x 16 KB = 64 KB
#define SMEM_TOTAL (32768 + 65536)     // 96 KB

__global__ __launch_bounds__(256, 2) void gemm_kernel(
    const float* __restrict__ X,   // [B, SEQ, HID]
    float* __restrict__ Y)         // [B, SEQ, HID]
{
    extern __shared__ char smem[];
    const uint32_t sb = smem_u32(smem);
    const int tid  = threadIdx.x;
    const int wid  = tid >> 5;
    const int lane = tid & 31;
    const int b    = blockIdx.z;
    const int row0 = blockIdx.y * 64;
    const int col0 = blockIdx.x * 128;

    // 8 warps: 2 (m) x 4 (n); warp tile 32 rows x 32 cols
    const int wm = (wid & 1) * 32;
    const int wn = (wid >> 1) * 32;

    const float*  A32 = X   + ((size_t)b * SEQ + row0) * HID;
    const __half* Bg  = g_B + ((size_t)b * HID + col0) * HID;

    // ---- load B: all 4 k-chunks (128 n-rows x 64 k each), 16 cp.async/thread
    {
        const int lr = tid >> 3;   // 0..31 (+32i)
        const int lc = tid & 7;    // 16B chunk
#pragma unroll
        for (int c = 0; c < 4; c++) {
#pragma unroll
            for (int i = 0; i < 4; i++) {
                int r = lr + i * 32;
                cp_async16(sb + OFF_B + (uint32_t)c * 16384 +
                               sw_off(r, lc * 8),
                           &Bg[(size_t)r * HID + c * 64 + lc * 8]);
            }
        }
        CP_COMMIT();
    }

    // ---- load + convert A: 64 rows x 256 k fp32 -> fp16 (one 64-float
    // chunk-row per thread: 16 batched LDG.128)
    {
        const int row = tid >> 2;          // 0..63
        const int ch  = tid & 3;           // k-chunk
        const float* ap = A32 + (size_t)row * HID + ch * 64;
        float4 v[16];
#pragma unroll
        for (int i = 0; i < 16; i++) v[i] = *(const float4*)&ap[i * 4];
#pragma unroll
        for (int i = 0; i < 16; i++) {
            __half2 h01 = __floats2half2_rn(v[i].x, v[i].y);
            __half2 h23 = __floats2half2_rn(v[i].z, v[i].w);
            uint2 p; p.x = *(uint32_t*)&h01; p.y = *(uint32_t*)&h23;
            *(uint2*)(smem + OFF_A + ch * 8192 + sw_off(row, i * 4)) = p;
        }
    }

    float acc[2][4][4];
#pragma unroll
    for (int i = 0; i < 2; i++)
#pragma unroll
        for (int j = 0; j < 4; j++)
#pragma unroll
            for (int q = 0; q < 4; q++) acc[i][j][q] = 0.f;

    CP_WAIT(0);
    __syncthreads();          // the ONLY barrier

    // ---- barrier-free mainloop: 16 k-steps over resident A and B
    const int arow = wm + (lane & 15);
    const int akof = (lane >> 4) << 3;
    const int bm   = lane >> 3;
    const int brq  = ((bm >> 1) << 3) + (lane & 7);
    const int bkof = (bm & 1) << 3;

#pragma unroll
    for (int c = 0; c < 4; c++) {
        const uint32_t aoff = sb + OFF_A + (uint32_t)c * 8192;
        const uint32_t boff = sb + OFF_B + (uint32_t)c * 16384;
#pragma unroll
        for (int s = 0; s < 4; s++) {
            uint32_t ah[2][4], bb[2][4];
            const int akk = s * 16 + akof;
#pragma unroll
            for (int mi = 0; mi < 2; mi++)
                ldmx4(aoff + sw_off(arow + mi * 16, akk), ah[mi]);
            const int bkq = s * 16 + bkof;
#pragma unroll
            for (int p = 0; p < 2; p++)
                ldmx4(boff + sw_off(wn + p * 16 + brq, bkq), bb[p]);
#pragma unroll
            for (int mi = 0; mi < 2; mi++)
#pragma unroll
                for (int p = 0; p < 2; p++) {
                    mma16816(acc[mi][p * 2 + 0], ah[mi], &bb[p][0]);
                    mma16816(acc[mi][p * 2 + 1], ah[mi], &bb[p][2]);
                }
        }
    }

    // ---- epilogue
    float* C = Y + ((size_t)b * SEQ + row0) * HID + col0;
#pragma unroll
    for (int mi = 0; mi < 2; mi++) {
        int r0 = wm + mi * 16 + (lane >> 2);
#pragma unroll
        for (int nj = 0; nj < 4; nj++) {
            int cc = wn + nj * 8 + (lane & 3) * 2;
            *(float2*)&C[(size_t)r0 * HID + cc]       = make_float2(acc[mi][nj][0], acc[mi][nj][1]);
            *(float2*)&C[(size_t)(r0 + 8) * HID + cc] = make_float2(acc[mi][nj][2], acc[mi][nj][3]);
        }
    }
}

// ===========================================================================
extern "C" void kernel_launch(void* const* d_in, const int* in_sizes, int n_in,
                              void* d_out, int out_size) {
    const float* x     = (const float*)d_in[0];  // [8, 4096, 256]
    const float* t     = (const float*)d_in[1];  // [8, 1]
    const float* osc   = (const float*)d_in[2];  // [6, 256, 256]
    const float* phase = (const float*)d_in[3];  // [6, 256]
    float* out = (float*)d_out;                  // [8, 4096, 256]
    (void)in_sizes; (void)n_in; (void)out_size;

    cudaFuncSetAttribute(gemm_kernel, cudaFuncAttributeMaxDynamicSharedMemorySize, SMEM_TOTAL);

    build_M_kernel<<<dim3(32, BATCH), 256>>>(osc, phase, t);
    gemm_kernel<<<dim3(2, SEQ / 64, BATCH), 256, SMEM_TOTAL>>>(x, out);
}